// round 14
// baseline (speedup 1.0000x reference)
#include <cuda_runtime.h>
#include <cuda_fp16.h>
#include <cstdint>

#define B 2
#define T 2048
#define C 1024
#define H 16
#define HD 64
#define BH (B * H)
#define N3 (3 * C)   // fused QKV output width = 3072

// ---- scratch (device globals; no runtime allocation allowed) ----
__device__ __half g_xh[(size_t)B * T * C];        // x in fp16
__device__ __half g_wi[(size_t)C * N3];           // interleaved W: [c][sel*1024+h*64+d]
__device__ __half g_woth[(size_t)C * C];          // Wo^T in fp16
__device__ __half g_qh[(size_t)BH * T * HD];      // Q pre-scaled by 0.125*log2e
__device__ __half g_kh[(size_t)BH * T * HD];
__device__ __half g_vh[(size_t)BH * T * HD];
__device__ __half g_oh[(size_t)B * T * C];        // attention out [B,T,H*HD]

// ---------------------------------------------------------------------------
// helpers
// ---------------------------------------------------------------------------
__device__ __forceinline__ unsigned f2h2(float lo, float hi) {
    unsigned r;
    asm("cvt.rn.f16x2.f32 %0, %1, %2;" : "=r"(r) : "f"(hi), "f"(lo));
    return r;
}
__device__ __forceinline__ float ex2f(float x) {
    float r;
    asm("ex2.approx.f32 %0, %1;" : "=f"(r) : "f"(x));
    return r;
}
__device__ __forceinline__ unsigned h2ex2(unsigned x) {
    unsigned r;
    asm("ex2.approx.f16x2 %0, %1;" : "=r"(r) : "r"(x));
    return r;
}
__device__ __forceinline__ void mma_f16(float c[4], const unsigned a[4], const unsigned b[2]) {
    asm("mma.sync.aligned.m16n8k16.row.col.f32.f16.f16.f32 "
        "{%0,%1,%2,%3},{%4,%5,%6,%7},{%8,%9},{%0,%1,%2,%3};"
        : "+f"(c[0]), "+f"(c[1]), "+f"(c[2]), "+f"(c[3])
        : "r"(a[0]), "r"(a[1]), "r"(a[2]), "r"(a[3]), "r"(b[0]), "r"(b[1]));
}
__device__ __forceinline__ void ldsm4(unsigned& d0, unsigned& d1, unsigned& d2, unsigned& d3,
                                      const void* p) {
    unsigned a = (unsigned)__cvta_generic_to_shared(p);
    asm volatile("ldmatrix.sync.aligned.m8n8.x4.shared.b16 {%0,%1,%2,%3}, [%4];"
                 : "=r"(d0), "=r"(d1), "=r"(d2), "=r"(d3) : "r"(a));
}
__device__ __forceinline__ void ldsm4t(unsigned& d0, unsigned& d1, unsigned& d2, unsigned& d3,
                                       const void* p) {
    unsigned a = (unsigned)__cvta_generic_to_shared(p);
    asm volatile("ldmatrix.sync.aligned.m8n8.x4.trans.shared.b16 {%0,%1,%2,%3}, [%4];"
                 : "=r"(d0), "=r"(d1), "=r"(d2), "=r"(d3) : "r"(a));
}
__device__ __forceinline__ void cp16(void* smem_dst, const void* gmem_src) {
    unsigned saddr = (unsigned)__cvta_generic_to_shared(smem_dst);
    asm volatile("cp.async.cg.shared.global [%0], [%1], 16;" :: "r"(saddr), "l"(gmem_src));
}
#define CP_COMMIT asm volatile("cp.async.commit_group;")
#define CP_WAIT(n) asm volatile("cp.async.wait_group %0;" :: "n"(n))

// ---------------------------------------------------------------------------
// Kernel P0: convert x to fp16; interleave Wq/Wk/Wv; transpose Wo. One launch.
// ---------------------------------------------------------------------------
__global__ void prep_kernel(const float* __restrict__ x,
                            const float* __restrict__ Wq,
                            const float* __restrict__ Wk,
                            const float* __restrict__ Wv,
                            const float* __restrict__ Wo) {
    int seg = blockIdx.y;
    if (seg == 4) {
        if (blockIdx.x >= 1024) return;
        __shared__ float tile[32][33];
        int xt = (blockIdx.x & 31) * 32, yt = (blockIdx.x >> 5) * 32;
        int tx = threadIdx.x & 31, ty = threadIdx.x >> 5;
#pragma unroll
        for (int i = 0; i < 32; i += 8)
            tile[ty + i][tx] = Wo[(size_t)(yt + ty + i) * C + xt + tx];
        __syncthreads();
#pragma unroll
        for (int i = 0; i < 32; i += 8)
            g_woth[(size_t)(xt + ty + i) * C + yt + tx] = __float2half(tile[tx][ty + i]);
        return;
    }
    int i = (blockIdx.x * 256 + threadIdx.x) * 4;
    if (seg == 0) {
        if (i < B * T * C) {
            float4 v = *(const float4*)&x[i];
            *(__half2*)&g_xh[i]     = __floats2half2_rn(v.x, v.y);
            *(__half2*)&g_xh[i + 2] = __floats2half2_rn(v.z, v.w);
        }
    } else {
        const float* src = seg == 1 ? Wq : seg == 2 ? Wk : Wv;
        if (i < H * C * HD) {
            float4 v = *(const float4*)&src[i];
            int d = i & 63, c = (i >> 6) & 1023, h = i >> 16;
            __half* dst = g_wi + ((size_t)c * N3 + (seg - 1) * 1024 + h * 64 + d);
            *(__half2*)&dst[0] = __floats2half2_rn(v.x, v.y);
            *(__half2*)&dst[2] = __floats2half2_rn(v.z, v.w);
        }
    }
}

// ---------------------------------------------------------------------------
// GEMM smem geometry (3-stage, dynamic): A[3][128][72], B[3][64][136]
// ---------------------------------------------------------------------------
#define GB_OFF (3 * 128 * 72)
#define GEMM_SMEM ((GB_OFF + 3 * 64 * 136) * 2)   // 107520 bytes

// ---------------------------------------------------------------------------
// Kernel 1: fused QKV GEMM [4096 x 3072 x 1024] (unchanged from R13)
// ---------------------------------------------------------------------------
__global__ void __launch_bounds__(256) qkv_kernel() {
    extern __shared__ __half smg[];
    __half (*As)[72]  = (__half(*)[72])smg;
    __half (*Bs)[136] = (__half(*)[136])(smg + GB_OFF);

    int n0 = blockIdx.x * 128;
    int m0 = blockIdx.y * 128;

    const __half* A = g_xh + (size_t)m0 * C;
    const __half* Bp = g_wi + n0;

    int tid = threadIdx.x;
    int lane = tid & 31, w = tid >> 5;
    int g = lane >> 2, tq = lane & 3;
    int wm = (w & 3) * 32, wn = (w >> 2) * 64;
    int mi = lane >> 3, mrow = lane & 7;
    int mb = mi & 1, kb = mi >> 1;

    float acc[2][8][4] = {};

    const int NC = C / 64;
#pragma unroll
    for (int pc = 0; pc < 2; pc++) {
        int k0 = pc * 64;
#pragma unroll
        for (int it = 0; it < 4; it++) {
            int f = tid + it * 256;
            int r = f >> 3, c8 = f & 7;
            cp16(&As[pc * 128 + r][c8 * 8], &A[(size_t)r * C + k0 + c8 * 8]);
        }
#pragma unroll
        for (int it = 0; it < 4; it++) {
            int f = tid + it * 256;
            int r = f >> 4, c8 = f & 15;
            cp16(&Bs[pc * 64 + r][c8 * 8], &Bp[(size_t)(k0 + r) * N3 + c8 * 8]);
        }
        CP_COMMIT;
    }

    for (int c = 0; c < NC; c++) {
        int st = c % 3;
        if (c + 1 < NC) CP_WAIT(1); else CP_WAIT(0);
        __syncthreads();
        if (c + 2 < NC) {
            int k0 = (c + 2) * 64, s2 = (c + 2) % 3;
#pragma unroll
            for (int it = 0; it < 4; it++) {
                int f = tid + it * 256;
                int r = f >> 3, c8 = f & 7;
                cp16(&As[s2 * 128 + r][c8 * 8], &A[(size_t)r * C + k0 + c8 * 8]);
            }
#pragma unroll
            for (int it = 0; it < 4; it++) {
                int f = tid + it * 256;
                int r = f >> 4, c8 = f & 15;
                cp16(&Bs[s2 * 64 + r][c8 * 8], &Bp[(size_t)(k0 + r) * N3 + c8 * 8]);
            }
            CP_COMMIT;
        }

#pragma unroll
        for (int ks = 0; ks < 4; ks++) {
            unsigned af[2][4], bf[8][2];
#pragma unroll
            for (int sm = 0; sm < 2; sm++)
                ldsm4(af[sm][0], af[sm][1], af[sm][2], af[sm][3],
                      &As[st * 128 + wm + sm * 16 + mb * 8 + mrow][ks * 16 + kb * 8]);
#pragma unroll
            for (int snp = 0; snp < 4; snp++)
                ldsm4t(bf[snp * 2][0], bf[snp * 2][1], bf[snp * 2 + 1][0], bf[snp * 2 + 1][1],
                       &Bs[st * 64 + ks * 16 + mb * 8 + mrow][wn + snp * 16 + kb * 8]);
#pragma unroll
            for (int sm = 0; sm < 2; sm++)
#pragma unroll
                for (int sn = 0; sn < 8; sn++)
                    mma_f16(acc[sm][sn], af[sm], bf[sn]);
        }
    }

    int sel = n0 >> 10;
    __half* outb = sel == 0 ? g_qh : sel == 1 ? g_kh : g_vh;
    float scl = (sel == 0) ? 0.18033688f : 1.f;   // 0.125 * log2(e)
#pragma unroll
    for (int sm = 0; sm < 2; sm++) {
        int m = m0 + wm + sm * 16 + g;
        int b = m >> 11, t = m & 2047;
#pragma unroll
        for (int sn = 0; sn < 8; sn++) {
            int nn = (n0 & 1023) + wn + sn * 8 + tq * 2;
            int h = nn >> 6, d = nn & 63;
            __half* p0 = outb + (((size_t)(b * 16 + h) * T + t) * HD + d);
            *(unsigned*)p0 = f2h2(acc[sm][sn][0] * scl, acc[sm][sn][1] * scl);
            *(unsigned*)(p0 + 8 * HD) = f2h2(acc[sm][sn][2] * scl, acc[sm][sn][3] * scl);
        }
    }
}

// ---------------------------------------------------------------------------
// Kernel 2: causal flash attention, FA2 shape: 4 warps, 128 q-rows/block,
// 32 q-rows per warp (two m16 blocks). K/V fragments reused across both
// row blocks -> mma:ldsm ratio 4:1. 3-buffer K/V ring, exp2 softmax,
// row sums via ones-MMA, P in registers.
// ---------------------------------------------------------------------------
#define AQ 128
#define AK 64
#define AVS_OFF (3 * AK * 72)
#define ATTN_SMEM ((AVS_OFF * 2) * 2)   // 55296 bytes

__global__ void __launch_bounds__(128) attn_kernel() {
    extern __shared__ __half sma[];
    __half (*Ks)[72] = (__half(*)[72])sma;
    __half (*Vs)[72] = (__half(*)[72])(sma + AVS_OFF);

    int bh = blockIdx.y;
    int qt = gridDim.x - 1 - blockIdx.x;   // heavy q-tiles first
    int t0 = qt * AQ;
    int tid = threadIdx.x;
    int lane = tid & 31, w = tid >> 5;
    int g = lane >> 2, tq = lane & 3;
    int wq = w * 32;                        // warp owns rows [wq, wq+32)
    int mi = lane >> 3, mrow = lane & 7;
    int mb = mi & 1, sb = mi >> 1;

    const __half* qb = g_qh + ((size_t)bh * T + t0) * HD;
    const __half* kb = g_kh + (size_t)bh * T * HD;
    const __half* vb = g_vh + (size_t)bh * T * HD;

    // Q fragments: two m16 blocks per warp
    unsigned qf[4][2][4];
#pragma unroll
    for (int ks = 0; ks < 4; ks++)
#pragma unroll
        for (int m2 = 0; m2 < 2; m2++) {
            int r0 = wq + m2 * 16 + g;
            qf[ks][m2][0] = *(const unsigned*)&qb[(size_t)r0 * HD + ks * 16 + 2 * tq];
            qf[ks][m2][1] = *(const unsigned*)&qb[(size_t)(r0 + 8) * HD + ks * 16 + 2 * tq];
            qf[ks][m2][2] = *(const unsigned*)&qb[(size_t)r0 * HD + ks * 16 + 2 * tq + 8];
            qf[ks][m2][3] = *(const unsigned*)&qb[(size_t)(r0 + 8) * HD + ks * 16 + 2 * tq + 8];
        }

    float m[4] = {-1e30f, -1e30f, -1e30f, -1e30f};   // [m2*2 + half]
    float l[4] = {};
    float accO[2][8][4] = {};

    int ntiles = 2 * qt + 2;   // keys 0 .. t0+127

    // prologue: prefetch tiles 0 and (if present) 1
#pragma unroll
    for (int it = 0; it < 4; it++) {
        int f = tid + it * 128;
        int r = f >> 3, c8 = f & 7;
        cp16(&Ks[r][c8 * 8], &kb[(size_t)r * HD + c8 * 8]);
        cp16(&Vs[r][c8 * 8], &vb[(size_t)r * HD + c8 * 8]);
    }
    CP_COMMIT;
    if (ntiles > 1) {
#pragma unroll
        for (int it = 0; it < 4; it++) {
            int f = tid + it * 128;
            int r = f >> 3, c8 = f & 7;
            cp16(&Ks[64 + r][c8 * 8], &kb[(size_t)(AK + r) * HD + c8 * 8]);
            cp16(&Vs[64 + r][c8 * 8], &vb[(size_t)(AK + r) * HD + c8 * 8]);
        }
        CP_COMMIT;
    }

    for (int itile = 0; itile < ntiles; itile++) {
        int buf = itile % 3;
        int s0 = itile * AK;
        if (itile + 1 < ntiles) CP_WAIT(1); else CP_WAIT(0);
        __syncthreads();
        if (itile + 2 < ntiles) {
            int sn0 = (itile + 2) * AK, b2 = (itile + 2) % 3;
#pragma unroll
            for (int it = 0; it < 4; it++) {
                int f = tid + it * 128;
                int r = f >> 3, c8 = f & 7;
                cp16(&Ks[b2 * 64 + r][c8 * 8], &kb[(size_t)(sn0 + r) * HD + c8 * 8]);
                cp16(&Vs[b2 * 64 + r][c8 * 8], &vb[(size_t)(sn0 + r) * HD + c8 * 8]);
            }
            CP_COMMIT;
        }

        if (s0 > t0 + wq + 31) continue;   // tile entirely in this warp's future

        // S = Q * K^T : K frags loaded once, used by BOTH row blocks
        float sc[2][8][4] = {};
#pragma unroll
        for (int ks = 0; ks < 4; ks++) {
            unsigned kf[8][2];
#pragma unroll
            for (int snp = 0; snp < 4; snp++) {
                unsigned b0, b1, b2, b3;
                ldsm4(b0, b1, b2, b3,
                      &Ks[buf * 64 + snp * 16 + sb * 8 + mrow][ks * 16 + mb * 8]);
                kf[snp * 2][0] = b0; kf[snp * 2][1] = b1;
                kf[snp * 2 + 1][0] = b2; kf[snp * 2 + 1][1] = b3;
            }
#pragma unroll
            for (int m2 = 0; m2 < 2; m2++)
#pragma unroll
                for (int sn = 0; sn < 8; sn++)
                    mma_f16(sc[m2][sn], qf[ks][m2], kf[sn]);
        }

        // causal mask on tiles crossing the warp's rows
        if (s0 + 63 > t0 + wq) {
#pragma unroll
            for (int m2 = 0; m2 < 2; m2++) {
                int r0 = t0 + wq + m2 * 16 + g, r1 = r0 + 8;
#pragma unroll
                for (int sn = 0; sn < 8; sn++) {
                    int c0 = s0 + sn * 8 + tq * 2, c1 = c0 + 1;
                    if (c0 > r0) sc[m2][sn][0] = -1e30f;
                    if (c1 > r0) sc[m2][sn][1] = -1e30f;
                    if (c0 > r1) sc[m2][sn][2] = -1e30f;
                    if (c1 > r1) sc[m2][sn][3] = -1e30f;
                }
            }
        }

        // running max (fp32), quad shfl reduce, 4 row groups
        float rx[4] = {-1e30f, -1e30f, -1e30f, -1e30f};
#pragma unroll
        for (int m2 = 0; m2 < 2; m2++)
#pragma unroll
            for (int sn = 0; sn < 8; sn++) {
                rx[m2 * 2]     = fmaxf(rx[m2 * 2], fmaxf(sc[m2][sn][0], sc[m2][sn][1]));
                rx[m2 * 2 + 1] = fmaxf(rx[m2 * 2 + 1], fmaxf(sc[m2][sn][2], sc[m2][sn][3]));
            }
        float corr[4];
#pragma unroll
        for (int i = 0; i < 4; i++) {
            rx[i] = fmaxf(rx[i], __shfl_xor_sync(0xffffffffu, rx[i], 1));
            rx[i] = fmaxf(rx[i], __shfl_xor_sync(0xffffffffu, rx[i], 2));
            float mn = fmaxf(m[i], rx[i]);
            corr[i] = ex2f(m[i] - mn);
            m[i] = mn;
        }

        // p = 2^(s-m) in fp16x2, directly in PV A-fragment registers
        unsigned ph[2][2][8];   // [m2][half][sn]
#pragma unroll
        for (int m2 = 0; m2 < 2; m2++)
#pragma unroll
            for (int sn = 0; sn < 8; sn++) {
                ph[m2][0][sn] = h2ex2(f2h2(sc[m2][sn][0] - m[m2 * 2],
                                           sc[m2][sn][1] - m[m2 * 2]));
                ph[m2][1][sn] = h2ex2(f2h2(sc[m2][sn][2] - m[m2 * 2 + 1],
                                           sc[m2][sn][3] - m[m2 * 2 + 1]));
            }

        // row sums via MMA against all-ones B fragment
        const unsigned ONE2 = 0x3C003C00u;
        unsigned onesb[2] = {ONE2, ONE2};
#pragma unroll
        for (int m2 = 0; m2 < 2; m2++) {
            float rs[4] = {0.f, 0.f, 0.f, 0.f};
#pragma unroll
            for (int kc = 0; kc < 4; kc++) {
                unsigned af[4] = {ph[m2][0][2 * kc], ph[m2][1][2 * kc],
                                  ph[m2][0][2 * kc + 1], ph[m2][1][2 * kc + 1]};
                mma_f16(rs, af, onesb);
            }
            l[m2 * 2]     = l[m2 * 2] * corr[m2 * 2] + rs[0];
            l[m2 * 2 + 1] = l[m2 * 2 + 1] * corr[m2 * 2 + 1] + rs[2];
#pragma unroll
            for (int sn = 0; sn < 8; sn++) {
                accO[m2][sn][0] *= corr[m2 * 2];     accO[m2][sn][1] *= corr[m2 * 2];
                accO[m2][sn][2] *= corr[m2 * 2 + 1]; accO[m2][sn][3] *= corr[m2 * 2 + 1];
            }
        }

        // O += P * V : V frags loaded once, used by BOTH row blocks
#pragma unroll
        for (int kc = 0; kc < 4; kc++) {
            unsigned vf[8][2];
#pragma unroll
            for (int snp = 0; snp < 4; snp++) {
                unsigned b0, b1, b2, b3;
                ldsm4t(b0, b1, b2, b3,
                       &Vs[buf * 64 + kc * 16 + mb * 8 + mrow][(snp * 2 + sb) * 8]);
                vf[snp * 2][0] = b0; vf[snp * 2][1] = b1;
                vf[snp * 2 + 1][0] = b2; vf[snp * 2 + 1][1] = b3;
            }
#pragma unroll
            for (int m2 = 0; m2 < 2; m2++) {
                unsigned af[4] = {ph[m2][0][2 * kc], ph[m2][1][2 * kc],
                                  ph[m2][0][2 * kc + 1], ph[m2][1][2 * kc + 1]};
#pragma unroll
                for (int sn = 0; sn < 8; sn++)
                    mma_f16(accO[m2][sn], af, vf[sn]);
            }
        }
    }

    // epilogue: normalize, write fp16 to [B,T,H*HD]
    int b = bh >> 4, h = bh & 15;
#pragma unroll
    for (int m2 = 0; m2 < 2; m2++) {
        float inv0 = 1.f / l[m2 * 2], inv1 = 1.f / l[m2 * 2 + 1];
        __half* o0 = g_oh + ((size_t)b * T + t0 + wq + m2 * 16 + g) * C + h * HD;
        __half* o1 = o0 + (size_t)8 * C;
#pragma unroll
        for (int sn = 0; sn < 8; sn++) {
            int cc = sn * 8 + tq * 2;
            *(unsigned*)&o0[cc] = f2h2(accO[m2][sn][0] * inv0, accO[m2][sn][1] * inv0);
            *(unsigned*)&o1[cc] = f2h2(accO[m2][sn][2] * inv1, accO[m2][sn][3] * inv1);
        }
    }
}

// ---------------------------------------------------------------------------
// Kernel 3: output projection [4096 x 1024 x 1024] (unchanged from R13)
// ---------------------------------------------------------------------------
__global__ void __launch_bounds__(256) proj_kernel(
    const float* __restrict__ bo, float* __restrict__ Y)
{
    extern __shared__ __half smg[];
    __half (*As)[72]  = (__half(*)[72])smg;
    __half (*Bs)[136] = (__half(*)[136])(smg + GB_OFF);

    int n0 = blockIdx.x * 128;
    int m0 = blockIdx.y * 128;

    const __half* A = g_oh + (size_t)m0 * C;
    const __half* Bp = g_woth + n0;

    int tid = threadIdx.x;
    int lane = tid & 31, w = tid >> 5;
    int g = lane >> 2, tq = lane & 3;
    int wm = (w & 3) * 32, wn = (w >> 2) * 64;
    int mi = lane >> 3, mrow = lane & 7;
    int mb = mi & 1, kb = mi >> 1;

    float acc[2][8][4] = {};

    const int NC = C / 64;
#pragma unroll
    for (int pc = 0; pc < 2; pc++) {
        int k0 = pc * 64;
#pragma unroll
        for (int it = 0; it < 4; it++) {
            int f = tid + it * 256;
            int r = f >> 3, c8 = f & 7;
            cp16(&As[pc * 128 + r][c8 * 8], &A[(size_t)r * C + k0 + c8 * 8]);
        }
#pragma unroll
        for (int it = 0; it < 4; it++) {
            int f = tid + it * 256;
            int r = f >> 4, c8 = f & 15;
            cp16(&Bs[pc * 64 + r][c8 * 8], &Bp[(size_t)(k0 + r) * C + c8 * 8]);
        }
        CP_COMMIT;
    }

    for (int c = 0; c < NC; c++) {
        int st = c % 3;
        if (c + 1 < NC) CP_WAIT(1); else CP_WAIT(0);
        __syncthreads();
        if (c + 2 < NC) {
            int k0 = (c + 2) * 64, s2 = (c + 2) % 3;
#pragma unroll
            for (int it = 0; it < 4; it++) {
                int f = tid + it * 256;
                int r = f >> 3, c8 = f & 7;
                cp16(&As[s2 * 128 + r][c8 * 8], &A[(size_t)r * C + k0 + c8 * 8]);
            }
#pragma unroll
            for (int it = 0; it < 4; it++) {
                int f = tid + it * 256;
                int r = f >> 4, c8 = f & 15;
                cp16(&Bs[s2 * 64 + r][c8 * 8], &Bp[(size_t)(k0 + r) * C + c8 * 8]);
            }
            CP_COMMIT;
        }

#pragma unroll
        for (int ks = 0; ks < 4; ks++) {
            unsigned af[2][4], bf[8][2];
#pragma unroll
            for (int sm = 0; sm < 2; sm++)
                ldsm4(af[sm][0], af[sm][1], af[sm][2], af[sm][3],
                      &As[st * 128 + wm + sm * 16 + mb * 8 + mrow][ks * 16 + kb * 8]);
#pragma unroll
            for (int snp = 0; snp < 4; snp++)
                ldsm4t(bf[snp * 2][0], bf[snp * 2][1], bf[snp * 2 + 1][0], bf[snp * 2 + 1][1],
                       &Bs[st * 64 + ks * 16 + mb * 8 + mrow][wn + snp * 16 + kb * 8]);
#pragma unroll
            for (int sm = 0; sm < 2; sm++)
#pragma unroll
                for (int sn = 0; sn < 8; sn++)
                    mma_f16(acc[sm][sn], af[sm], bf[sn]);
        }
    }

#pragma unroll
    for (int sm = 0; sm < 2; sm++) {
        int r0 = m0 + wm + sm * 16 + g;
#pragma unroll
        for (int sn = 0; sn < 8; sn++) {
            int cc = n0 + wn + sn * 8 + tq * 2;
            float b0 = bo[cc], b1 = bo[cc + 1];
            *(float2*)&Y[(size_t)r0 * C + cc] =
                make_float2(acc[sm][sn][0] + b0, acc[sm][sn][1] + b1);
            *(float2*)&Y[(size_t)(r0 + 8) * C + cc] =
                make_float2(acc[sm][sn][2] + b0, acc[sm][sn][3] + b1);
        }
    }
}

// ---------------------------------------------------------------------------
extern "C" void kernel_launch(void* const* d_in, const int* in_sizes, int n_in,
                              void* d_out, int out_size)
{
    const float* x  = (const float*)d_in[0];
    const float* Wq = (const float*)d_in[1];
    const float* Wk = (const float*)d_in[2];
    const float* Wv = (const float*)d_in[3];
    const float* Wo = (const float*)d_in[4];
    const float* bo = (const float*)d_in[5];
    float* y = (float*)d_out;

    static bool attr_done = false;
    if (!attr_done) {
        cudaFuncSetAttribute(qkv_kernel,
                             cudaFuncAttributeMaxDynamicSharedMemorySize, GEMM_SMEM);
        cudaFuncSetAttribute(proj_kernel,
                             cudaFuncAttributeMaxDynamicSharedMemorySize, GEMM_SMEM);
        cudaFuncSetAttribute(attn_kernel,
                             cudaFuncAttributeMaxDynamicSharedMemorySize, ATTN_SMEM);
        attr_done = true;
    }

    prep_kernel<<<dim3(4096, 5), 256>>>(x, Wq, Wk, Wv, Wo);
    qkv_kernel<<<dim3(N3 / 128, (B * T) / 128), 256, GEMM_SMEM>>>();
    attn_kernel<<<dim3(T / AQ, BH), 128, ATTN_SMEM>>>();
    proj_kernel<<<dim3(C / 128, (B * T) / 128), 256, GEMM_SMEM>>>(bo, y);
}

// round 15
// speedup vs baseline: 1.0196x; 1.0196x over previous
#include <cuda_runtime.h>
#include <cuda_fp16.h>
#include <cstdint>

#define B 2
#define T 2048
#define C 1024
#define H 16
#define HD 64
#define BH (B * H)
#define N3 (3 * C)   // fused QKV output width = 3072

// ---- scratch (device globals; no runtime allocation allowed) ----
__device__ __half g_xh[(size_t)B * T * C];        // x in fp16
__device__ __half g_wi[(size_t)C * N3];           // interleaved W: [c][sel*1024+h*64+d]
__device__ __half g_woth[(size_t)C * C];          // Wo^T in fp16
__device__ __half g_qh[(size_t)BH * T * HD];      // Q pre-scaled by 0.125*log2e
__device__ __half g_kh[(size_t)BH * T * HD];
__device__ __half g_vh[(size_t)BH * T * HD];
__device__ __half g_oh[(size_t)B * T * C];        // attention out [B,T,H*HD]

// ---------------------------------------------------------------------------
// helpers
// ---------------------------------------------------------------------------
__device__ __forceinline__ unsigned f2h2(float lo, float hi) {
    unsigned r;
    asm("cvt.rn.f16x2.f32 %0, %1, %2;" : "=r"(r) : "f"(hi), "f"(lo));
    return r;
}
__device__ __forceinline__ float ex2f(float x) {
    float r;
    asm("ex2.approx.f32 %0, %1;" : "=f"(r) : "f"(x));
    return r;
}
__device__ __forceinline__ unsigned h2ex2(unsigned x) {
    unsigned r;
    asm("ex2.approx.f16x2 %0, %1;" : "=r"(r) : "r"(x));
    return r;
}
__device__ __forceinline__ void mma_f16(float c[4], const unsigned a[4], const unsigned b[2]) {
    asm("mma.sync.aligned.m16n8k16.row.col.f32.f16.f16.f32 "
        "{%0,%1,%2,%3},{%4,%5,%6,%7},{%8,%9},{%0,%1,%2,%3};"
        : "+f"(c[0]), "+f"(c[1]), "+f"(c[2]), "+f"(c[3])
        : "r"(a[0]), "r"(a[1]), "r"(a[2]), "r"(a[3]), "r"(b[0]), "r"(b[1]));
}
__device__ __forceinline__ void ldsm4(unsigned& d0, unsigned& d1, unsigned& d2, unsigned& d3,
                                      const void* p) {
    unsigned a = (unsigned)__cvta_generic_to_shared(p);
    asm volatile("ldmatrix.sync.aligned.m8n8.x4.shared.b16 {%0,%1,%2,%3}, [%4];"
                 : "=r"(d0), "=r"(d1), "=r"(d2), "=r"(d3) : "r"(a));
}
__device__ __forceinline__ void ldsm4t(unsigned& d0, unsigned& d1, unsigned& d2, unsigned& d3,
                                       const void* p) {
    unsigned a = (unsigned)__cvta_generic_to_shared(p);
    asm volatile("ldmatrix.sync.aligned.m8n8.x4.trans.shared.b16 {%0,%1,%2,%3}, [%4];"
                 : "=r"(d0), "=r"(d1), "=r"(d2), "=r"(d3) : "r"(a));
}
__device__ __forceinline__ void cp16(void* smem_dst, const void* gmem_src) {
    unsigned saddr = (unsigned)__cvta_generic_to_shared(smem_dst);
    asm volatile("cp.async.cg.shared.global [%0], [%1], 16;" :: "r"(saddr), "l"(gmem_src));
}
#define CP_COMMIT asm volatile("cp.async.commit_group;")
#define CP_WAIT(n) asm volatile("cp.async.wait_group %0;" :: "n"(n))

// ---------------------------------------------------------------------------
// Kernel P0: convert x to fp16; interleave Wq/Wk/Wv; transpose Wo. One launch.
// ---------------------------------------------------------------------------
__global__ void prep_kernel(const float* __restrict__ x,
                            const float* __restrict__ Wq,
                            const float* __restrict__ Wk,
                            const float* __restrict__ Wv,
                            const float* __restrict__ Wo) {
    int seg = blockIdx.y;
    if (seg == 4) {
        if (blockIdx.x >= 1024) return;
        __shared__ float tile[32][33];
        int xt = (blockIdx.x & 31) * 32, yt = (blockIdx.x >> 5) * 32;
        int tx = threadIdx.x & 31, ty = threadIdx.x >> 5;
#pragma unroll
        for (int i = 0; i < 32; i += 8)
            tile[ty + i][tx] = Wo[(size_t)(yt + ty + i) * C + xt + tx];
        __syncthreads();
#pragma unroll
        for (int i = 0; i < 32; i += 8)
            g_woth[(size_t)(xt + ty + i) * C + yt + tx] = __float2half(tile[tx][ty + i]);
        return;
    }
    int i = (blockIdx.x * 256 + threadIdx.x) * 4;
    if (seg == 0) {
        if (i < B * T * C) {
            float4 v = *(const float4*)&x[i];
            *(__half2*)&g_xh[i]     = __floats2half2_rn(v.x, v.y);
            *(__half2*)&g_xh[i + 2] = __floats2half2_rn(v.z, v.w);
        }
    } else {
        const float* src = seg == 1 ? Wq : seg == 2 ? Wk : Wv;
        if (i < H * C * HD) {
            float4 v = *(const float4*)&src[i];
            int d = i & 63, c = (i >> 6) & 1023, h = i >> 16;
            __half* dst = g_wi + ((size_t)c * N3 + (seg - 1) * 1024 + h * 64 + d);
            *(__half2*)&dst[0] = __floats2half2_rn(v.x, v.y);
            *(__half2*)&dst[2] = __floats2half2_rn(v.z, v.w);
        }
    }
}

// ---------------------------------------------------------------------------
// GEMM smem geometry for qkv (3-stage): A[3][128][72], B[3][64][136]
// ---------------------------------------------------------------------------
#define GB_OFF (3 * 128 * 72)
#define GEMM_SMEM ((GB_OFF + 3 * 64 * 136) * 2)   // 107520 bytes

// ---------------------------------------------------------------------------
// Kernel 1: fused QKV GEMM [4096 x 3072 x 1024] (unchanged - at mma ceiling)
// ---------------------------------------------------------------------------
__global__ void __launch_bounds__(256) qkv_kernel() {
    extern __shared__ __half smg[];
    __half (*As)[72]  = (__half(*)[72])smg;
    __half (*Bs)[136] = (__half(*)[136])(smg + GB_OFF);

    int n0 = blockIdx.x * 128;
    int m0 = blockIdx.y * 128;

    const __half* A = g_xh + (size_t)m0 * C;
    const __half* Bp = g_wi + n0;

    int tid = threadIdx.x;
    int lane = tid & 31, w = tid >> 5;
    int g = lane >> 2, tq = lane & 3;
    int wm = (w & 3) * 32, wn = (w >> 2) * 64;
    int mi = lane >> 3, mrow = lane & 7;
    int mb = mi & 1, kb = mi >> 1;

    float acc[2][8][4] = {};

    const int NC = C / 64;
#pragma unroll
    for (int pc = 0; pc < 2; pc++) {
        int k0 = pc * 64;
#pragma unroll
        for (int it = 0; it < 4; it++) {
            int f = tid + it * 256;
            int r = f >> 3, c8 = f & 7;
            cp16(&As[pc * 128 + r][c8 * 8], &A[(size_t)r * C + k0 + c8 * 8]);
        }
#pragma unroll
        for (int it = 0; it < 4; it++) {
            int f = tid + it * 256;
            int r = f >> 4, c8 = f & 15;
            cp16(&Bs[pc * 64 + r][c8 * 8], &Bp[(size_t)(k0 + r) * N3 + c8 * 8]);
        }
        CP_COMMIT;
    }

    for (int c = 0; c < NC; c++) {
        int st = c % 3;
        if (c + 1 < NC) CP_WAIT(1); else CP_WAIT(0);
        __syncthreads();
        if (c + 2 < NC) {
            int k0 = (c + 2) * 64, s2 = (c + 2) % 3;
#pragma unroll
            for (int it = 0; it < 4; it++) {
                int f = tid + it * 256;
                int r = f >> 3, c8 = f & 7;
                cp16(&As[s2 * 128 + r][c8 * 8], &A[(size_t)r * C + k0 + c8 * 8]);
            }
#pragma unroll
            for (int it = 0; it < 4; it++) {
                int f = tid + it * 256;
                int r = f >> 4, c8 = f & 15;
                cp16(&Bs[s2 * 64 + r][c8 * 8], &Bp[(size_t)(k0 + r) * N3 + c8 * 8]);
            }
            CP_COMMIT;
        }

#pragma unroll
        for (int ks = 0; ks < 4; ks++) {
            unsigned af[2][4], bf[8][2];
#pragma unroll
            for (int sm = 0; sm < 2; sm++)
                ldsm4(af[sm][0], af[sm][1], af[sm][2], af[sm][3],
                      &As[st * 128 + wm + sm * 16 + mb * 8 + mrow][ks * 16 + kb * 8]);
#pragma unroll
            for (int snp = 0; snp < 4; snp++)
                ldsm4t(bf[snp * 2][0], bf[snp * 2][1], bf[snp * 2 + 1][0], bf[snp * 2 + 1][1],
                       &Bs[st * 64 + ks * 16 + mb * 8 + mrow][wn + snp * 16 + kb * 8]);
#pragma unroll
            for (int sm = 0; sm < 2; sm++)
#pragma unroll
                for (int sn = 0; sn < 8; sn++)
                    mma_f16(acc[sm][sn], af[sm], bf[sn]);
        }
    }

    int sel = n0 >> 10;
    __half* outb = sel == 0 ? g_qh : sel == 1 ? g_kh : g_vh;
    float scl = (sel == 0) ? 0.18033688f : 1.f;   // 0.125 * log2(e)
#pragma unroll
    for (int sm = 0; sm < 2; sm++) {
        int m = m0 + wm + sm * 16 + g;
        int b = m >> 11, t = m & 2047;
#pragma unroll
        for (int sn = 0; sn < 8; sn++) {
            int nn = (n0 & 1023) + wn + sn * 8 + tq * 2;
            int h = nn >> 6, d = nn & 63;
            __half* p0 = outb + (((size_t)(b * 16 + h) * T + t) * HD + d);
            *(unsigned*)p0 = f2h2(acc[sm][sn][0] * scl, acc[sm][sn][1] * scl);
            *(unsigned*)(p0 + 8 * HD) = f2h2(acc[sm][sn][2] * scl, acc[sm][sn][3] * scl);
        }
    }
}

// ---------------------------------------------------------------------------
// Kernel 2: causal flash attention (exact R13 version: 4 warps, 64 q-rows,
// 3-buffer K/V ring, exp2 softmax, ones-MMA row sums, P in registers).
// ---------------------------------------------------------------------------
#define AQ 64
#define AK 64
#define AVS_OFF (3 * AK * 72)
#define ATTN_SMEM ((AVS_OFF * 2) * 2)   // 55296 bytes

__global__ void __launch_bounds__(128, 4) attn_kernel() {
    extern __shared__ __half sma[];
    __half (*Ks)[72] = (__half(*)[72])sma;
    __half (*Vs)[72] = (__half(*)[72])(sma + AVS_OFF);

    int bh = blockIdx.y;
    int qt = gridDim.x - 1 - blockIdx.x;   // heavy q-tiles first
    int t0 = qt * AQ;
    int tid = threadIdx.x;
    int lane = tid & 31, w = tid >> 5;
    int g = lane >> 2, tq = lane & 3;
    int wq = w * 16;
    int mi = lane >> 3, mrow = lane & 7;
    int mb = mi & 1, sb = mi >> 1;

    const __half* qb = g_qh + ((size_t)bh * T + t0) * HD;
    const __half* kb = g_kh + (size_t)bh * T * HD;
    const __half* vb = g_vh + (size_t)bh * T * HD;

    unsigned qf[4][4];
#pragma unroll
    for (int ks = 0; ks < 4; ks++) {
        qf[ks][0] = *(const unsigned*)&qb[(size_t)(wq + g) * HD + ks * 16 + 2 * tq];
        qf[ks][1] = *(const unsigned*)&qb[(size_t)(wq + g + 8) * HD + ks * 16 + 2 * tq];
        qf[ks][2] = *(const unsigned*)&qb[(size_t)(wq + g) * HD + ks * 16 + 2 * tq + 8];
        qf[ks][3] = *(const unsigned*)&qb[(size_t)(wq + g + 8) * HD + ks * 16 + 2 * tq + 8];
    }

    float m0 = -1e30f, m1 = -1e30f, l0 = 0.f, l1 = 0.f;
    float accO[8][4] = {};

    int ntiles = qt + 1;   // keys 0 .. t0+63

#pragma unroll
    for (int it = 0; it < 4; it++) {
        int f = tid + it * 128;
        int r = f >> 3, c8 = f & 7;
        cp16(&Ks[r][c8 * 8], &kb[(size_t)r * HD + c8 * 8]);
        cp16(&Vs[r][c8 * 8], &vb[(size_t)r * HD + c8 * 8]);
    }
    CP_COMMIT;
    if (ntiles > 1) {
#pragma unroll
        for (int it = 0; it < 4; it++) {
            int f = tid + it * 128;
            int r = f >> 3, c8 = f & 7;
            cp16(&Ks[64 + r][c8 * 8], &kb[(size_t)(AK + r) * HD + c8 * 8]);
            cp16(&Vs[64 + r][c8 * 8], &vb[(size_t)(AK + r) * HD + c8 * 8]);
        }
        CP_COMMIT;
    }

    for (int itile = 0; itile < ntiles; itile++) {
        int buf = itile % 3;
        int s0 = itile * AK;
        if (itile + 1 < ntiles) CP_WAIT(1); else CP_WAIT(0);
        __syncthreads();
        if (itile + 2 < ntiles) {
            int sn0 = (itile + 2) * AK, b2 = (itile + 2) % 3;
#pragma unroll
            for (int it = 0; it < 4; it++) {
                int f = tid + it * 128;
                int r = f >> 3, c8 = f & 7;
                cp16(&Ks[b2 * 64 + r][c8 * 8], &kb[(size_t)(sn0 + r) * HD + c8 * 8]);
                cp16(&Vs[b2 * 64 + r][c8 * 8], &vb[(size_t)(sn0 + r) * HD + c8 * 8]);
            }
            CP_COMMIT;
        }

        float sc[8][4] = {};
#pragma unroll
        for (int ks = 0; ks < 4; ks++) {
#pragma unroll
            for (int snp = 0; snp < 4; snp++) {
                unsigned b0, b1, b2, b3;
                ldsm4(b0, b1, b2, b3,
                      &Ks[buf * 64 + snp * 16 + sb * 8 + mrow][ks * 16 + mb * 8]);
                unsigned bb0[2] = {b0, b1}, bb1[2] = {b2, b3};
                mma_f16(sc[snp * 2], qf[ks], bb0);
                mma_f16(sc[snp * 2 + 1], qf[ks], bb1);
            }
        }

        if (itile == ntiles - 1) {
            int r0 = t0 + wq + g, r1 = r0 + 8;
#pragma unroll
            for (int sn = 0; sn < 8; sn++) {
                int c0 = s0 + sn * 8 + tq * 2, c1 = c0 + 1;
                if (c0 > r0) sc[sn][0] = -1e30f;
                if (c1 > r0) sc[sn][1] = -1e30f;
                if (c0 > r1) sc[sn][2] = -1e30f;
                if (c1 > r1) sc[sn][3] = -1e30f;
            }
        }

        float rx0 = -1e30f, rx1 = -1e30f;
#pragma unroll
        for (int sn = 0; sn < 8; sn++) {
            rx0 = fmaxf(rx0, fmaxf(sc[sn][0], sc[sn][1]));
            rx1 = fmaxf(rx1, fmaxf(sc[sn][2], sc[sn][3]));
        }
        rx0 = fmaxf(rx0, __shfl_xor_sync(0xffffffffu, rx0, 1));
        rx0 = fmaxf(rx0, __shfl_xor_sync(0xffffffffu, rx0, 2));
        rx1 = fmaxf(rx1, __shfl_xor_sync(0xffffffffu, rx1, 1));
        rx1 = fmaxf(rx1, __shfl_xor_sync(0xffffffffu, rx1, 2));
        float mn0 = fmaxf(m0, rx0), mn1 = fmaxf(m1, rx1);
        float corr0 = ex2f(m0 - mn0), corr1 = ex2f(m1 - mn1);
        m0 = mn0; m1 = mn1;

        unsigned p0h[8], p1h[8];
#pragma unroll
        for (int sn = 0; sn < 8; sn++) {
            p0h[sn] = h2ex2(f2h2(sc[sn][0] - mn0, sc[sn][1] - mn0));
            p1h[sn] = h2ex2(f2h2(sc[sn][2] - mn1, sc[sn][3] - mn1));
        }

        const unsigned ONE2 = 0x3C003C00u;
        unsigned onesb[2] = {ONE2, ONE2};
        float rsacc[4] = {0.f, 0.f, 0.f, 0.f};
#pragma unroll
        for (int kc = 0; kc < 4; kc++) {
            unsigned af[4] = {p0h[2 * kc], p1h[2 * kc], p0h[2 * kc + 1], p1h[2 * kc + 1]};
            mma_f16(rsacc, af, onesb);
        }
        l0 = l0 * corr0 + rsacc[0];
        l1 = l1 * corr1 + rsacc[2];
#pragma unroll
        for (int sn = 0; sn < 8; sn++) {
            accO[sn][0] *= corr0; accO[sn][1] *= corr0;
            accO[sn][2] *= corr1; accO[sn][3] *= corr1;
        }

#pragma unroll
        for (int kc = 0; kc < 4; kc++) {
            unsigned af[4] = {p0h[2 * kc], p1h[2 * kc], p0h[2 * kc + 1], p1h[2 * kc + 1]};
#pragma unroll
            for (int snp = 0; snp < 4; snp++) {
                unsigned b0, b1, b2, b3;
                ldsm4t(b0, b1, b2, b3,
                       &Vs[buf * 64 + kc * 16 + mb * 8 + mrow][(snp * 2 + sb) * 8]);
                unsigned bb0[2] = {b0, b1}, bb1[2] = {b2, b3};
                mma_f16(accO[snp * 2], af, bb0);
                mma_f16(accO[snp * 2 + 1], af, bb1);
            }
        }
    }

    float inv0 = 1.f / l0, inv1 = 1.f / l1;
    int b = bh >> 4, h = bh & 15;
    __half* o0 = g_oh + ((size_t)b * T + t0 + wq + g) * C + h * HD;
    __half* o1 = o0 + (size_t)8 * C;
#pragma unroll
    for (int sn = 0; sn < 8; sn++) {
        int cc = sn * 8 + tq * 2;
        *(unsigned*)&o0[cc] = f2h2(accO[sn][0] * inv0, accO[sn][1] * inv0);
        *(unsigned*)&o1[cc] = f2h2(accO[sn][2] * inv1, accO[sn][3] * inv1);
    }
}

// ---------------------------------------------------------------------------
// Kernel 3: output projection [4096 x 1024 x 1024].
// Retiled: 64(M) x 128(N) per block, 128 threads (2x2 warps of 32x64),
// 2-stage cp.async -> 53.2 KB smem -> 4 CTAs/SM; grid 512 = one full wave.
// ---------------------------------------------------------------------------
#define PB_OFF (2 * 64 * 72)
#define PROJ_SMEM ((PB_OFF + 2 * 64 * 136) * 2)   // 53248 bytes

__global__ void __launch_bounds__(128) proj_kernel(
    const float* __restrict__ bo, float* __restrict__ Y)
{
    extern __shared__ __half smp[];
    __half (*As)[72]  = (__half(*)[72])smp;            // [2*64][72]
    __half (*Bs)[136] = (__half(*)[136])(smp + PB_OFF); // [2*64][136]

    int n0 = blockIdx.x * 128;
    int m0 = blockIdx.y * 64;

    const __half* A = g_oh + (size_t)m0 * C;
    const __half* Bp = g_woth + n0;

    int tid = threadIdx.x;
    int lane = tid & 31, w = tid >> 5;
    int g = lane >> 2, tq = lane & 3;
    int wm = (w & 1) * 32, wn = (w >> 1) * 64;
    int mi = lane >> 3, mrow = lane & 7;
    int mb = mi & 1, kb = mi >> 1;

    float acc[2][8][4] = {};

    const int NC = C / 64;
    // prefetch chunk 0 -> stage 0
#pragma unroll
    for (int it = 0; it < 4; it++) {
        int f = tid + it * 128;
        int r = f >> 3, c8 = f & 7;
        cp16(&As[r][c8 * 8], &A[(size_t)r * C + c8 * 8]);
    }
#pragma unroll
    for (int it = 0; it < 8; it++) {
        int f = tid + it * 128;
        int r = f >> 4, c8 = f & 15;
        cp16(&Bs[r][c8 * 8], &Bp[(size_t)r * C + c8 * 8]);
    }
    CP_COMMIT;

    for (int c = 0; c < NC; c++) {
        int st = c & 1;
        CP_WAIT(0);          // chunk c resident
        __syncthreads();     // visible; all warps done with buf st^1
        if (c + 1 < NC) {
            int k0 = (c + 1) * 64, s2 = st ^ 1;
#pragma unroll
            for (int it = 0; it < 4; it++) {
                int f = tid + it * 128;
                int r = f >> 3, c8 = f & 7;
                cp16(&As[s2 * 64 + r][c8 * 8], &A[(size_t)r * C + k0 + c8 * 8]);
            }
#pragma unroll
            for (int it = 0; it < 8; it++) {
                int f = tid + it * 128;
                int r = f >> 4, c8 = f & 15;
                cp16(&Bs[s2 * 64 + r][c8 * 8], &Bp[(size_t)(k0 + r) * C + c8 * 8]);
            }
            CP_COMMIT;
        }

#pragma unroll
        for (int ks = 0; ks < 4; ks++) {
            unsigned af[2][4], bf[8][2];
#pragma unroll
            for (int sm = 0; sm < 2; sm++)
                ldsm4(af[sm][0], af[sm][1], af[sm][2], af[sm][3],
                      &As[st * 64 + wm + sm * 16 + mb * 8 + mrow][ks * 16 + kb * 8]);
#pragma unroll
            for (int snp = 0; snp < 4; snp++)
                ldsm4t(bf[snp * 2][0], bf[snp * 2][1], bf[snp * 2 + 1][0], bf[snp * 2 + 1][1],
                       &Bs[st * 64 + ks * 16 + mb * 8 + mrow][wn + snp * 16 + kb * 8]);
#pragma unroll
            for (int sm = 0; sm < 2; sm++)
#pragma unroll
                for (int sn = 0; sn < 8; sn++)
                    mma_f16(acc[sm][sn], af[sm], bf[sn]);
        }
    }

#pragma unroll
    for (int sm = 0; sm < 2; sm++) {
        int r0 = m0 + wm + sm * 16 + g;
#pragma unroll
        for (int sn = 0; sn < 8; sn++) {
            int cc = n0 + wn + sn * 8 + tq * 2;
            float b0 = bo[cc], b1 = bo[cc + 1];
            *(float2*)&Y[(size_t)r0 * C + cc] =
                make_float2(acc[sm][sn][0] + b0, acc[sm][sn][1] + b1);
            *(float2*)&Y[(size_t)(r0 + 8) * C + cc] =
                make_float2(acc[sm][sn][2] + b0, acc[sm][sn][3] + b1);
        }
    }
}

// ---------------------------------------------------------------------------
extern "C" void kernel_launch(void* const* d_in, const int* in_sizes, int n_in,
                              void* d_out, int out_size)
{
    const float* x  = (const float*)d_in[0];
    const float* Wq = (const float*)d_in[1];
    const float* Wk = (const float*)d_in[2];
    const float* Wv = (const float*)d_in[3];
    const float* Wo = (const float*)d_in[4];
    const float* bo = (const float*)d_in[5];
    float* y = (float*)d_out;

    static bool attr_done = false;
    if (!attr_done) {
        cudaFuncSetAttribute(qkv_kernel,
                             cudaFuncAttributeMaxDynamicSharedMemorySize, GEMM_SMEM);
        cudaFuncSetAttribute(proj_kernel,
                             cudaFuncAttributeMaxDynamicSharedMemorySize, PROJ_SMEM);
        cudaFuncSetAttribute(attn_kernel,
                             cudaFuncAttributeMaxDynamicSharedMemorySize, ATTN_SMEM);
        attr_done = true;
    }

    prep_kernel<<<dim3(4096, 5), 256>>>(x, Wq, Wk, Wv, Wo);
    qkv_kernel<<<dim3(N3 / 128, (B * T) / 128), 256, GEMM_SMEM>>>();
    attn_kernel<<<dim3(T / AQ, BH), 128, ATTN_SMEM>>>();
    proj_kernel<<<dim3(C / 128, (B * T) / 64), 128, PROJ_SMEM>>>(bo, y);
}